// round 7
// baseline (speedup 1.0000x reference)
#include <cuda_runtime.h>
#include <cuda_bf16.h>

#define NT 128              // 4 warps per block
#define PPT 1               // 1 point per thread -> max sym-phase parallelism
#define PTS_PER_BLK (NT * PPT)   // 128
#define MAXPAIR 512         // max q-pairs in shared (P<=1024)
#define MARGIN 0.01f
#define FIXED_SCALE 4294967296.0

// Deterministic order-independent accumulator + completion counter.
// Last block publishes and resets, so graph replays start clean.
__device__ long long    g_acc;
__device__ unsigned int g_count;

struct Rot { float r[9]; };

__device__ __forceinline__ Rot quat_rot(const float* __restrict__ q) {
    float s = q[0], u = q[1], v = q[2], w = q[3];
    Rot R;
    R.r[0] = 1.f - 2.f * (v * v + w * w);
    R.r[1] = 2.f * (u * v - s * w);
    R.r[2] = 2.f * (u * w + s * v);
    R.r[3] = 2.f * (u * v + s * w);
    R.r[4] = 1.f - 2.f * (u * u + w * w);
    R.r[5] = 2.f * (v * w - s * u);
    R.r[6] = 2.f * (u * w - s * v);
    R.r[7] = 2.f * (v * w + s * u);
    R.r[8] = 1.f - 2.f * (u * u + v * v);
    return R;
}

// ---- packed f32x2 helpers (Blackwell FFMA2: 2 fp32 MACs / instruction) ----
__device__ __forceinline__ double ffma2(double a, double b, double c) {
    double d;
    asm("fma.rn.f32x2 %0, %1, %2, %3;"
        : "=d"(d) : "d"(a), "d"(b), "d"(c));
    return d;
}
__device__ __forceinline__ double splat2(float x) {
    double d;
    asm("mov.b64 %0, {%1, %1};" : "=d"(d) : "f"(x));
    return d;
}
__device__ __forceinline__ float lo32(double d) {
    return __int_as_float(__double2loint(d));
}
__device__ __forceinline__ float hi32(double d) {
    return __int_as_float(__double2hiint(d));
}

__global__ void __launch_bounds__(NT)
add_loss_kernel(const float* __restrict__ poses_pred,
                const float* __restrict__ poses_target,
                const int*   __restrict__ labels,
                const float* __restrict__ points,
                const int*   __restrict__ symmetry,
                float* __restrict__ out,
                int B, int C, int P, int S)
{
    const int b   = blockIdx.x;
    const int yc  = blockIdx.y;
    const int tid = threadIdx.x;
    const unsigned int total_blocks = gridDim.x * gridDim.y;

    // q-pair tile: sA[j]=(x_2j, x_2j+1, y_2j, y_2j+1), sB[j]=(z0,z1,||x2_0||^2,||x2_1||^2)
    __shared__ float4 sA[MAXPAIR];
    __shared__ float4 sB[MAXPAIR];
    __shared__ double swarp[NT / 32];

    const int label = labels[b];
    double lsum = 0.0;

    if (label > 0) {
        const float* q1 = poses_pred   + ((size_t)b * C + label) * 4;
        const float* q2 = poses_target + ((size_t)b * C + label) * 4;
        Rot R1 = quat_rot(q1);
        Rot R2 = quat_rot(q2);
        const float* mp = points + (size_t)label * P * 3;
        const bool sym = symmetry[label] > 0;

        const int p = yc * PTS_PER_BLK + tid;   // this thread's point

        if (!sym) {
            // ADD: matched-point distance, reference formulation
            if (p < P) {
                float a = mp[3 * p], bb = mp[3 * p + 1], c = mp[3 * p + 2];
                float x1x = R1.r[0]*a + R1.r[1]*bb + R1.r[2]*c;
                float x1y = R1.r[3]*a + R1.r[4]*bb + R1.r[5]*c;
                float x1z = R1.r[6]*a + R1.r[7]*bb + R1.r[8]*c;
                float x2x = R2.r[0]*a + R2.r[1]*bb + R2.r[2]*c;
                float x2y = R2.r[3]*a + R2.r[4]*bb + R2.r[5]*c;
                float x2z = R2.r[6]*a + R2.r[7]*bb + R2.r[8]*c;
                float dx = x1x - x2x, dy = x1y - x2y, dz = x1z - x2z;
                float d = dx*dx + dy*dy + dz*dz;
                lsum = (double)fmaxf(0.5f * d - MARGIN, 0.f);
            }
        } else {
            const int npairs = P >> 1;
            // fill full x2 tile as q-pairs (shared by 4 warps; 4 iters/thread)
            for (int j = tid; j < npairs; j += NT) {
                int qa = 2 * j, qb = 2 * j + 1;
                float a0 = mp[3*qa], b0 = mp[3*qa+1], c0 = mp[3*qa+2];
                float a1 = mp[3*qb], b1 = mp[3*qb+1], c1 = mp[3*qb+2];
                float x0 = R2.r[0]*a0 + R2.r[1]*b0 + R2.r[2]*c0;
                float y0 = R2.r[3]*a0 + R2.r[4]*b0 + R2.r[5]*c0;
                float z0 = R2.r[6]*a0 + R2.r[7]*b0 + R2.r[8]*c0;
                float x1 = R2.r[0]*a1 + R2.r[1]*b1 + R2.r[2]*c1;
                float y1 = R2.r[3]*a1 + R2.r[4]*b1 + R2.r[5]*c1;
                float z1 = R2.r[6]*a1 + R2.r[7]*b1 + R2.r[8]*c1;
                sA[j] = make_float4(x0, x1, y0, y1);
                sB[j] = make_float4(z0, z1,
                                    x0*x0 + y0*y0 + z0*z0,
                                    x1*x1 + y1*y1 + z1*z1);
            }
            __syncthreads();

            // per-thread point data: splat -2*x1 into f32x2
            float n1 = 0.f;
            double Ax = 0, Ay = 0, Az = 0;
            if (p < P) {
                float a = mp[3*p], bb = mp[3*p+1], c = mp[3*p+2];
                float x = R1.r[0]*a + R1.r[1]*bb + R1.r[2]*c;
                float y = R1.r[3]*a + R1.r[4]*bb + R1.r[5]*c;
                float z = R1.r[6]*a + R1.r[7]*bb + R1.r[8]*c;
                Ax = splat2(-2.f*x); Ay = splat2(-2.f*y); Az = splat2(-2.f*z);
                n1 = x*x + y*y + z*z;
            }

            // min over q: packed 2-q FFMA2; unroll 4 -> 8 independent min chains
            const float INF = 3.4028235e38f;
            float m0 = INF, m1 = INF;
            const double2* __restrict__ pA = (const double2*)sA;  // (x01, y01)
            const double2* __restrict__ pB = (const double2*)sB;  // (z01, w01)
            #pragma unroll 4
            for (int j = 0; j < npairs; j++) {
                double2 v1 = pA[j];
                double2 v2 = pB[j];
                double t = ffma2(Ax, v1.x, ffma2(Ay, v1.y, ffma2(Az, v2.x, v2.y)));
                m0 = fminf(m0, lo32(t));
                m1 = fminf(m1, hi32(t));
            }
            float mn = fminf(m0, m1);

            if (p < P) lsum = (double)fmaxf(0.5f * (n1 + mn) - MARGIN, 0.f);
        }
    }

    // ---- block reduction: warp shuffle, then across 4 warps ----
    const int lane = tid & 31;
    const int wid  = tid >> 5;
    #pragma unroll
    for (int off = 16; off > 0; off >>= 1)
        lsum += __shfl_down_sync(0xFFFFFFFFu, lsum, off);
    if (lane == 0) swarp[wid] = lsum;
    __syncthreads();

    if (tid == 0) {
        double bsum = 0.0;
        #pragma unroll
        for (int w = 0; w < NT / 32; w++) bsum += swarp[w];

        long long contrib = (long long)llrint(bsum * FIXED_SCALE);
        if (contrib != 0) atomicAdd((unsigned long long*)&g_acc, (unsigned long long)contrib);
        __threadfence();

        unsigned int prev = atomicAdd(&g_count, 1u);
        if (prev == total_blocks - 1) {
            long long acc = (long long)atomicAdd((unsigned long long*)&g_acc, 0ull);
            out[0] = (float)(((double)acc / FIXED_SCALE) / ((double)B * (double)P));
            g_acc = 0;
            g_count = 0;
            __threadfence();
        }
    }
}

extern "C" void kernel_launch(void* const* d_in, const int* in_sizes, int n_in,
                              void* d_out, int out_size)
{
    const float* poses_pred   = (const float*)d_in[0];
    const float* poses_target = (const float*)d_in[1];
    const int*   poses_labels = (const int*)d_in[2];
    const float* points       = (const float*)d_in[3];
    const int*   symmetry     = (const int*)d_in[4];
    float* out = (float*)d_out;

    const int B = in_sizes[2];                 // labels: [B]
    const int C = in_sizes[4];                 // symmetry: [C]
    const int P = in_sizes[3] / (C * 3);       // points: [C,P,3]
    const int S = (P + PTS_PER_BLK - 1) / PTS_PER_BLK;

    dim3 grid(B, S);
    add_loss_kernel<<<grid, NT>>>(poses_pred, poses_target, poses_labels,
                                  points, symmetry, out, B, C, P, S);
}